// round 2
// baseline (speedup 1.0000x reference)
#include <cuda_runtime.h>
#include <math.h>

#define BATCH 16
#define CC    512
#define NPIX  4096   // 64*64
#define MPIX  1024   // 32*32

// ---------------- scratch (device globals; no allocation) ----------------
__device__ float g_Wcat[384 * 512];                        // [theta;phi;g] weights
__device__ float g_Y[(size_t)BATCH * 384 * NPIX];          // full-res projections
__device__ float g_phi[(size_t)BATCH * 64 * MPIX];         // pooled phi  [b][d][m]
__device__ float g_gt[(size_t)BATCH * MPIX * 256];         // pooled g, transposed [b][m][v]
__device__ float g_o[(size_t)BATCH * 256 * NPIX];          // attention output [b][v][n]

// ---------------- weight concat ----------------
__global__ void catw_kernel(const float* __restrict__ wt, const float* __restrict__ wp,
                            const float* __restrict__ wg)
{
    int t = blockIdx.x * blockDim.x + threadIdx.x;
    if (t >= 384 * 512) return;
    int row = t >> 9;
    float v;
    if (row < 64)       v = wt[t];
    else if (row < 128) v = wp[t - 64 * 512];
    else                v = wg[t - 128 * 512];
    g_Wcat[t] = v;
}

// ---------------- tiled SGEMM: C[b] = A @ B[b] (+ optional gamma*acc + resid) ----
// A: [M x K] row-major (shared over batch), B: [K x N] row-major per batch,
// C: [M x N] per batch. M % 128 == 0, N % 128 == 0, K % 8 == 0.
#define BM 128
#define BN 128
#define BKK 8
__global__ void __launch_bounds__(256, 2) sgemm_kernel(
    const float* __restrict__ A, const float* __restrict__ Bbase, float* __restrict__ Cbase,
    int M, int K, int N,
    const float* __restrict__ gamma, const float* __restrict__ resid)
{
    int b = blockIdx.z;
    const float* B = Bbase + (size_t)b * K * N;
    float* C = Cbase + (size_t)b * M * N;
    int m0 = blockIdx.y * BM;
    int n0 = blockIdx.x * BN;

    __shared__ float As[BKK][BM];
    __shared__ float Bs[BKK][BN];

    int tx = threadIdx.x;
    int tr = tx >> 4;        // 0..15  (row group of 8)
    int tc = tx & 15;        // 0..15  (col group of 8)

    // global-load mapping
    int am = tx >> 1;            // 0..127
    int ak = (tx & 1) * 4;       // 0 or 4
    int bk = tx >> 5;            // 0..7
    int bn = (tx & 31) * 4;      // 0..124

    float acc[8][8];
#pragma unroll
    for (int i = 0; i < 8; i++)
#pragma unroll
        for (int j = 0; j < 8; j++) acc[i][j] = 0.f;

    for (int k0 = 0; k0 < K; k0 += BKK) {
        float4 av = *(const float4*)&A[(size_t)(m0 + am) * K + k0 + ak];
        float4 bv = *(const float4*)&B[(size_t)(k0 + bk) * N + n0 + bn];
        __syncthreads();
        As[ak + 0][am] = av.x; As[ak + 1][am] = av.y;
        As[ak + 2][am] = av.z; As[ak + 3][am] = av.w;
        *(float4*)&Bs[bk][bn] = bv;
        __syncthreads();
#pragma unroll
        for (int kk = 0; kk < BKK; kk++) {
            float ar[8], br[8];
            *(float4*)(ar)     = *(float4*)&As[kk][tr * 8];
            *(float4*)(ar + 4) = *(float4*)&As[kk][tr * 8 + 4];
            *(float4*)(br)     = *(float4*)&Bs[kk][tc * 8];
            *(float4*)(br + 4) = *(float4*)&Bs[kk][tc * 8 + 4];
#pragma unroll
            for (int i = 0; i < 8; i++)
#pragma unroll
                for (int j = 0; j < 8; j++)
                    acc[i][j] += ar[i] * br[j];
        }
    }

    if (resid != nullptr) {
        float gm = gamma[0];
#pragma unroll
        for (int i = 0; i < 8; i++) {
            int m = m0 + tr * 8 + i;
            const float* rrow = resid + (size_t)b * M * N + (size_t)m * N + n0 + tc * 8;
            float* crow = C + (size_t)m * N + n0 + tc * 8;
#pragma unroll
            for (int j = 0; j < 8; j++)
                crow[j] = gm * acc[i][j] + rrow[j];
        }
    } else {
#pragma unroll
        for (int i = 0; i < 8; i++) {
            int m = m0 + tr * 8 + i;
            float* crow = C + (size_t)m * N + n0 + tc * 8;
#pragma unroll
            for (int j = 0; j < 8; j++)
                crow[j] = acc[i][j];
        }
    }
}

// ---------------- 2x2 maxpool of phi/g rows of Y ----------------
// Y rows: [0,64)=theta, [64,128)=phi full-res, [128,384)=g full-res
__global__ void pool_kernel()
{
    int t = blockIdx.x * blockDim.x + threadIdx.x;
    if (t >= BATCH * 320 * MPIX) return;
    int m  = t & (MPIX - 1);
    int ch = (t >> 10) % 320;      // 0..319
    int b  = t / (320 * MPIX);
    int ph = m >> 5, pw = m & 31;
    const float* row = g_Y + ((size_t)b * 384 + 64 + ch) * NPIX;
    int n00 = (ph * 2) * 64 + pw * 2;
    float v = fmaxf(fmaxf(row[n00], row[n00 + 1]),
                    fmaxf(row[n00 + 64], row[n00 + 65]));
    if (ch < 64)
        g_phi[((size_t)b * 64 + ch) * MPIX + m] = v;
    else
        g_gt[((size_t)b * MPIX + m) * 256 + (ch - 64)] = v;
}

// ---------------- fused attention ----------------
// block = (n-tile of 32 queries, batch). smem: S[32][1024], theta[64][32], chunk[8192]
#define ATTN_SMEM (32 * 1024 * 4 + 64 * 32 * 4 + 8192 * 4)
__global__ void __launch_bounds__(256, 1) attn_kernel()
{
    extern __shared__ float sm[];
    float* S  = sm;                  // 32 x 1024
    float* ts = sm + 32 * 1024;      // 64 x 32 (theta tile, [d][n])
    float* cs = ts + 64 * 32;        // 8192 floats: phi chunk [64][128] / g chunk [32][256]

    int b   = blockIdx.y;
    int n0g = blockIdx.x * 32;
    int tx  = threadIdx.x;

    const float* th = g_Y + (size_t)b * 384 * NPIX;   // rows 0..63 = theta
    // load theta tile
    for (int l = tx; l < 64 * 32; l += 256) {
        int d = l >> 5, n = l & 31;
        ts[d * 32 + n] = th[(size_t)d * NPIX + n0g + n];
    }
    __syncthreads();

    // ---- phase 1: scores S[n][m] ----
    {
        const float* ph = g_phi + (size_t)b * 64 * MPIX;
        int mg = tx & 31, ng = tx >> 5;    // ng 0..7
        for (int mc = 0; mc < MPIX; mc += 128) {
            __syncthreads();
#pragma unroll
            for (int j = 0; j < 8; j++) {
                int id = tx + 256 * j;               // float4 id, 2048 total
                int d = id >> 5, c = id & 31;
                *(float4*)&cs[d * 128 + c * 4] =
                    *(const float4*)&ph[(size_t)d * MPIX + mc + c * 4];
            }
            __syncthreads();
            float a[4][4];
#pragma unroll
            for (int i = 0; i < 4; i++)
#pragma unroll
                for (int j = 0; j < 4; j++) a[i][j] = 0.f;
#pragma unroll 8
            for (int d = 0; d < 64; d++) {
                float tn[4], pm[4];
                *(float4*)tn = *(float4*)&ts[d * 32 + ng * 4];
                *(float4*)pm = *(float4*)&cs[d * 128 + mg * 4];
#pragma unroll
                for (int i = 0; i < 4; i++)
#pragma unroll
                    for (int j = 0; j < 4; j++)
                        a[i][j] += tn[i] * pm[j];
            }
#pragma unroll
            for (int i = 0; i < 4; i++) {
                float4 v = make_float4(a[i][0], a[i][1], a[i][2], a[i][3]);
                *(float4*)&S[(size_t)(ng * 4 + i) * 1024 + mc + mg * 4] = v;
            }
        }
    }
    __syncthreads();

    // ---- phase 2: softmax over m (rows of S) ----
    {
        int warp = tx >> 5, lane = tx & 31;
        for (int r = warp * 4; r < warp * 4 + 4; r++) {
            float* row = S + (size_t)r * 1024;
            float mx = -1e30f;
            for (int i = lane; i < 1024; i += 32) mx = fmaxf(mx, row[i]);
#pragma unroll
            for (int off = 16; off; off >>= 1)
                mx = fmaxf(mx, __shfl_xor_sync(0xFFFFFFFFu, mx, off));
            float sum = 0.f;
            for (int i = lane; i < 1024; i += 32) {
                float e = __expf(row[i] - mx);
                row[i] = e;
                sum += e;
            }
#pragma unroll
            for (int off = 16; off; off >>= 1)
                sum += __shfl_xor_sync(0xFFFFFFFFu, sum, off);
            float inv = 1.f / sum;
            for (int i = lane; i < 1024; i += 32) row[i] *= inv;
        }
    }
    __syncthreads();

    // ---- phase 3: O[v][n] = sum_m g[v][m] * P[n][m] ----
    {
        const float* g = g_gt + (size_t)b * MPIX * 256;   // [m][v]
        int vg = tx & 31, ng = tx >> 5;                 // v0 = vg*8, n-block = ng*4
        float acc[4][8];
#pragma unroll
        for (int r = 0; r < 4; r++)
#pragma unroll
            for (int k = 0; k < 8; k++) acc[r][k] = 0.f;

        for (int mc = 0; mc < MPIX; mc += 32) {
            __syncthreads();
            const float4* src = (const float4*)(g + (size_t)mc * 256);
#pragma unroll
            for (int j = 0; j < 8; j++) {
                int id = tx + 256 * j;     // 2048 float4
                ((float4*)cs)[id] = src[id];
            }
            __syncthreads();
#pragma unroll 4
            for (int i = 0; i < 32; i++) {
                float p[4];
#pragma unroll
                for (int r = 0; r < 4; r++)
                    p[r] = S[(size_t)(ng * 4 + r) * 1024 + mc + i];
                float gv[8];
                *(float4*)(gv)     = *(float4*)&cs[i * 256 + vg * 8];
                *(float4*)(gv + 4) = *(float4*)&cs[i * 256 + vg * 8 + 4];
#pragma unroll
                for (int r = 0; r < 4; r++)
#pragma unroll
                    for (int k = 0; k < 8; k++)
                        acc[r][k] += p[r] * gv[k];
            }
        }

        float* ob = g_o + (size_t)b * 256 * NPIX;
#pragma unroll
        for (int k = 0; k < 8; k++)
#pragma unroll
            for (int r = 0; r < 4; r++)
                ob[(size_t)(vg * 8 + k) * NPIX + n0g + ng * 4 + r] = acc[r][k];
    }
}

// ---------------- launch ----------------
extern "C" void kernel_launch(void* const* d_in, const int* in_sizes, int n_in,
                              void* d_out, int out_size)
{
    const float* x      = (const float*)d_in[0];
    const float* wtheta = (const float*)d_in[1];
    const float* wphi   = (const float*)d_in[2];
    const float* wg     = (const float*)d_in[3];
    const float* wo     = (const float*)d_in[4];
    const float* gamma  = (const float*)d_in[5];
    float* out = (float*)d_out;

    float *dW, *dY, *dO;
    cudaGetSymbolAddress((void**)&dW, g_Wcat);
    cudaGetSymbolAddress((void**)&dY, g_Y);
    cudaGetSymbolAddress((void**)&dO, g_o);

    cudaFuncSetAttribute(attn_kernel,
                         cudaFuncAttributeMaxDynamicSharedMemorySize, ATTN_SMEM);

    // 1) concat weights
    catw_kernel<<<(384 * 512 + 255) / 256, 256>>>(wtheta, wphi, wg);

    // 2) projections: Y[b] = Wcat @ x[b]   (M=384, K=512, N=4096)
    {
        dim3 grid(NPIX / BN, 384 / BM, BATCH);
        sgemm_kernel<<<grid, 256>>>(dW, x, dY, 384, 512, NPIX, nullptr, nullptr);
    }

    // 3) 2x2 maxpool -> phi_p, g_t
    pool_kernel<<<(BATCH * 320 * MPIX + 255) / 256, 256>>>();

    // 4) fused attention -> o
    {
        dim3 grid(NPIX / 32, BATCH);
        attn_kernel<<<grid, 256, ATTN_SMEM>>>();
    }

    // 5) out = gamma * (w_o @ o) + x   (M=512, K=256, N=4096)
    {
        dim3 grid(NPIX / BN, 512 / BM, BATCH);
        sgemm_kernel<<<grid, 256>>>(wo, dO, out, 512, 256, NPIX, gamma, x);
    }
}

// round 3
// speedup vs baseline: 2.3580x; 2.3580x over previous
#include <cuda_runtime.h>
#include <math.h>

#define BATCH 16
#define NPIX  4096   // 64*64
#define MPIX  1024   // 32*32

// ---------------- scratch (device globals; no allocation) ----------------
__device__ float g_Wcat[384 * 512];                        // [theta;phi;g] weights
__device__ float g_Y[(size_t)BATCH * 384 * NPIX];          // full-res projections
__device__ float g_phi[(size_t)BATCH * 64 * MPIX];         // pooled phi  [b][d][m]  (tf32)
__device__ float g_gt[(size_t)BATCH * MPIX * 256];         // pooled g    [b][m][v]  (tf32)
__device__ float g_o[(size_t)BATCH * 256 * NPIX];          // attention output [b][v][n]

// ---------------- tf32 helpers ----------------
__device__ __forceinline__ float to_tf32(float x) {
    float r;
    asm("cvt.rna.tf32.f32 %0, %1;" : "=f"(r) : "f"(x));
    return r;
}

__device__ __forceinline__ void mma_tf32(float* d,
                                         const float* a, const float* b,
                                         const float* c)
{
    asm volatile(
        "mma.sync.aligned.m16n8k8.row.col.f32.tf32.tf32.f32 "
        "{%0,%1,%2,%3}, {%4,%5,%6,%7}, {%8,%9}, {%10,%11,%12,%13};\n"
        : "=f"(d[0]), "=f"(d[1]), "=f"(d[2]), "=f"(d[3])
        : "r"(__float_as_uint(a[0])), "r"(__float_as_uint(a[1])),
          "r"(__float_as_uint(a[2])), "r"(__float_as_uint(a[3])),
          "r"(__float_as_uint(b[0])), "r"(__float_as_uint(b[1])),
          "f"(c[0]), "f"(c[1]), "f"(c[2]), "f"(c[3]));
}

// ---------------- weight concat ----------------
__global__ void catw_kernel(const float* __restrict__ wt, const float* __restrict__ wp,
                            const float* __restrict__ wg)
{
    int t = blockIdx.x * blockDim.x + threadIdx.x;
    if (t >= 384 * 512) return;
    int row = t >> 9;
    float v;
    if (row < 64)       v = wt[t];
    else if (row < 128) v = wp[t - 64 * 512];
    else                v = wg[t - 128 * 512];
    g_Wcat[t] = v;
}

// ---------------- TF32 tensor-core GEMM ----------------
// C[b] = A @ B[b]  (+ optional gamma*acc + resid)
// A: [M x K] row-major (shared over batch), B: [K x N] row-major per batch.
// M%128==0, N%128==0, K%16==0.
#define BM 128
#define BN 128
#define BK 16
#define AS_STRIDE 20
#define BS_STRIDE 132
__global__ void __launch_bounds__(256, 2) gemm_tf32_kernel(
    const float* __restrict__ A, const float* __restrict__ Bbase, float* __restrict__ Cbase,
    int M, int K, int N,
    const float* __restrict__ gamma, const float* __restrict__ resid)
{
    int b = blockIdx.z;
    const float* B = Bbase + (size_t)b * K * N;
    float* C = Cbase + (size_t)b * M * N;
    int m0 = blockIdx.y * BM;
    int n0 = blockIdx.x * BN;

    __shared__ float As[BM][AS_STRIDE];   // [m][k] padded
    __shared__ float Bs[BK][BS_STRIDE];   // [k][n] padded

    int tx   = threadIdx.x;
    int wid  = tx >> 5;
    int lane = tx & 31;
    int gid  = lane >> 2;      // 0..7
    int tig  = lane & 3;       // 0..3
    int wm0  = (wid & 1) * 64; // warp m offset (2 warps along M)
    int wn0  = (wid >> 1) * 32;// warp n offset (4 warps along N)

    float acc[4][4][4];
#pragma unroll
    for (int i = 0; i < 4; i++)
#pragma unroll
        for (int j = 0; j < 4; j++)
#pragma unroll
            for (int q = 0; q < 4; q++) acc[i][j][q] = 0.f;

    // global-load index mapping
    // A tile: 128x16 floats = 512 float4; B tile: 16x128 = 512 float4
    int a_row[2], a_col[2], b_row[2], b_col[2];
#pragma unroll
    for (int r = 0; r < 2; r++) {
        int idx = tx + 256 * r;
        a_row[r] = idx >> 2;  a_col[r] = (idx & 3) * 4;
        b_row[r] = idx >> 5;  b_col[r] = (idx & 31) * 4;
    }

    float4 pa[2], pb[2];
#pragma unroll
    for (int r = 0; r < 2; r++) {
        pa[r] = *(const float4*)&A[(size_t)(m0 + a_row[r]) * K + a_col[r]];
        pb[r] = *(const float4*)&B[(size_t)b_row[r] * N + n0 + b_col[r]];
    }

    for (int k0 = 0; k0 < K; k0 += BK) {
        __syncthreads();
#pragma unroll
        for (int r = 0; r < 2; r++) {
            float4 va = pa[r], vb = pb[r];
            va.x = to_tf32(va.x); va.y = to_tf32(va.y);
            va.z = to_tf32(va.z); va.w = to_tf32(va.w);
            vb.x = to_tf32(vb.x); vb.y = to_tf32(vb.y);
            vb.z = to_tf32(vb.z); vb.w = to_tf32(vb.w);
            *(float4*)&As[a_row[r]][a_col[r]] = va;
            *(float4*)&Bs[b_row[r]][b_col[r]] = vb;
        }
        __syncthreads();

        if (k0 + BK < K) {
#pragma unroll
            for (int r = 0; r < 2; r++) {
                pa[r] = *(const float4*)&A[(size_t)(m0 + a_row[r]) * K + k0 + BK + a_col[r]];
                pb[r] = *(const float4*)&B[(size_t)(k0 + BK + b_row[r]) * N + n0 + b_col[r]];
            }
        }

#pragma unroll
        for (int ks = 0; ks < BK; ks += 8) {
            float af[4][4];
#pragma unroll
            for (int i = 0; i < 4; i++) {
                int base = wm0 + 16 * i;
                af[i][0] = As[base + gid][ks + tig];
                af[i][1] = As[base + gid + 8][ks + tig];
                af[i][2] = As[base + gid][ks + tig + 4];
                af[i][3] = As[base + gid + 8][ks + tig + 4];
            }
            float bf[4][2];
#pragma unroll
            for (int j = 0; j < 4; j++) {
                bf[j][0] = Bs[ks + tig][wn0 + 8 * j + gid];
                bf[j][1] = Bs[ks + tig + 4][wn0 + 8 * j + gid];
            }
#pragma unroll
            for (int i = 0; i < 4; i++)
#pragma unroll
                for (int j = 0; j < 4; j++)
                    mma_tf32(acc[i][j], af[i], bf[j], acc[i][j]);
        }
    }

    // epilogue
    if (resid != nullptr) {
        float gm = gamma[0];
#pragma unroll
        for (int i = 0; i < 4; i++) {
            int r0 = m0 + wm0 + 16 * i + gid;
#pragma unroll
            for (int j = 0; j < 4; j++) {
                int cc = n0 + wn0 + 8 * j + 2 * tig;
                const float* rr0 = resid + (size_t)b * M * N + (size_t)r0 * N + cc;
                const float* rr1 = rr0 + 8 * N;
                float2 v0 = make_float2(gm * acc[i][j][0] + rr0[0], gm * acc[i][j][1] + rr0[1]);
                float2 v1 = make_float2(gm * acc[i][j][2] + rr1[0], gm * acc[i][j][3] + rr1[1]);
                *(float2*)&C[(size_t)r0 * N + cc]       = v0;
                *(float2*)&C[(size_t)(r0 + 8) * N + cc] = v1;
            }
        }
    } else {
#pragma unroll
        for (int i = 0; i < 4; i++) {
            int r0 = m0 + wm0 + 16 * i + gid;
#pragma unroll
            for (int j = 0; j < 4; j++) {
                int cc = n0 + wn0 + 8 * j + 2 * tig;
                *(float2*)&C[(size_t)r0 * N + cc]       = make_float2(acc[i][j][0], acc[i][j][1]);
                *(float2*)&C[(size_t)(r0 + 8) * N + cc] = make_float2(acc[i][j][2], acc[i][j][3]);
            }
        }
    }
}

// ---------------- 2x2 maxpool (writes tf32-rounded values) ----------------
__global__ void pool_kernel()
{
    int t = blockIdx.x * blockDim.x + threadIdx.x;
    if (t >= BATCH * 320 * MPIX) return;
    int m  = t & (MPIX - 1);
    int ch = (t >> 10) % 320;
    int b  = t / (320 * MPIX);
    int ph = m >> 5, pw = m & 31;
    const float* row = g_Y + ((size_t)b * 384 + 64 + ch) * NPIX;
    int n00 = (ph * 2) * 64 + pw * 2;
    float v = fmaxf(fmaxf(row[n00], row[n00 + 1]),
                    fmaxf(row[n00 + 64], row[n00 + 65]));
    v = to_tf32(v);
    if (ch < 64)
        g_phi[((size_t)b * 64 + ch) * MPIX + m] = v;
    else
        g_gt[((size_t)b * MPIX + m) * 256 + (ch - 64)] = v;
}

// ---------------- fused attention (tensor-core phases) ----------------
// block = (32-query tile, batch), 256 threads.
// smem floats: S[32][1028], ts[32][68], cs[8448]
#define SP 1028
#define TSP 68
#define ATTN_SMEM ((32 * SP + 32 * TSP + 8448) * 4)
__global__ void __launch_bounds__(256, 1) attn_kernel()
{
    extern __shared__ float sm[];
    float* S  = sm;                    // scores/beta [32][SP]
    float* ts = sm + 32 * SP;          // theta tile  [n][TSP]
    float* cs = ts + 32 * TSP;         // staging chunk

    int b    = blockIdx.y;
    int n0g  = blockIdx.x * 32;
    int tx   = threadIdx.x;
    int wid  = tx >> 5;
    int lane = tx & 31;
    int gid  = lane >> 2;
    int tig  = lane & 3;

    // load theta tile [n][d] (tf32-rounded)
    {
        const float* th = g_Y + (size_t)b * 384 * NPIX;
        for (int l = tx; l < 32 * 64; l += 256) {
            int n = l & 31, d = l >> 5;
            ts[n * TSP + d] = to_tf32(th[(size_t)d * NPIX + n0g + n]);
        }
    }

    // ---- phase 1: S[n][m] = theta^T phi (MMA) ----
    {
        const float* ph = g_phi + (size_t)b * 64 * MPIX;
        int wn0 = wid * 16;                       // 8 warps x 16 m-cols
        for (int mc = 0; mc < MPIX; mc += 128) {
            __syncthreads();
#pragma unroll
            for (int r = 0; r < 8; r++) {
                int idx = tx + 256 * r;           // 2048 float4
                int d = idx >> 5, c4 = (idx & 31) * 4;
                *(float4*)&cs[d * 132 + c4] =
                    *(const float4*)&ph[(size_t)d * MPIX + mc + c4];
            }
            __syncthreads();

            float sacc[2][2][4];
#pragma unroll
            for (int i = 0; i < 2; i++)
#pragma unroll
                for (int j = 0; j < 2; j++)
#pragma unroll
                    for (int q = 0; q < 4; q++) sacc[i][j][q] = 0.f;

#pragma unroll
            for (int ks = 0; ks < 64; ks += 8) {
                float af[2][4];
#pragma unroll
                for (int i = 0; i < 2; i++) {
                    int base = 16 * i;
                    af[i][0] = ts[(base + gid) * TSP + ks + tig];
                    af[i][1] = ts[(base + gid + 8) * TSP + ks + tig];
                    af[i][2] = ts[(base + gid) * TSP + ks + tig + 4];
                    af[i][3] = ts[(base + gid + 8) * TSP + ks + tig + 4];
                }
                float bf[2][2];
#pragma unroll
                for (int j = 0; j < 2; j++) {
                    bf[j][0] = cs[(ks + tig) * 132 + wn0 + 8 * j + gid];
                    bf[j][1] = cs[(ks + tig + 4) * 132 + wn0 + 8 * j + gid];
                }
#pragma unroll
                for (int i = 0; i < 2; i++)
#pragma unroll
                    for (int j = 0; j < 2; j++)
                        mma_tf32(sacc[i][j], af[i], bf[j], sacc[i][j]);
            }
#pragma unroll
            for (int i = 0; i < 2; i++)
#pragma unroll
                for (int j = 0; j < 2; j++) {
                    int rr = 16 * i + gid;
                    int cc = mc + wn0 + 8 * j + 2 * tig;
                    S[rr * SP + cc]           = sacc[i][j][0];
                    S[rr * SP + cc + 1]       = sacc[i][j][1];
                    S[(rr + 8) * SP + cc]     = sacc[i][j][2];
                    S[(rr + 8) * SP + cc + 1] = sacc[i][j][3];
                }
        }
    }
    __syncthreads();

    // ---- phase 2: softmax over m; write back tf32(beta) ----
    {
        for (int r = wid * 4; r < wid * 4 + 4; r++) {
            float* row = S + (size_t)r * SP;
            float mx = -1e30f;
            for (int i = lane; i < 1024; i += 32) mx = fmaxf(mx, row[i]);
#pragma unroll
            for (int off = 16; off; off >>= 1)
                mx = fmaxf(mx, __shfl_xor_sync(0xFFFFFFFFu, mx, off));
            float sum = 0.f;
            for (int i = lane; i < 1024; i += 32) {
                float e = __expf(row[i] - mx);
                row[i] = e;
                sum += e;
            }
#pragma unroll
            for (int off = 16; off; off >>= 1)
                sum += __shfl_xor_sync(0xFFFFFFFFu, sum, off);
            float inv = 1.f / sum;
            for (int i = lane; i < 1024; i += 32) row[i] = to_tf32(row[i] * inv);
        }
    }
    __syncthreads();

    // ---- phase 3: O[n][v] = beta @ g  (MMA) ----
    {
        const float* g = g_gt + (size_t)b * MPIX * 256;   // [m][v], tf32
        int wv0 = wid * 32;                               // 8 warps x 32 v
        float acc3[2][4][4];
#pragma unroll
        for (int i = 0; i < 2; i++)
#pragma unroll
            for (int j = 0; j < 4; j++)
#pragma unroll
                for (int q = 0; q < 4; q++) acc3[i][j][q] = 0.f;

        for (int mc = 0; mc < MPIX; mc += 32) {
            __syncthreads();
#pragma unroll
            for (int r = 0; r < 8; r++) {
                int idx = tx + 256 * r;                   // 2048 float4
                int mm = idx >> 6, c4 = (idx & 63) * 4;
                *(float4*)&cs[mm * 260 + c4] =
                    *(const float4*)&g[(size_t)(mc + mm) * 256 + c4];
            }
            __syncthreads();

#pragma unroll
            for (int ks = 0; ks < 32; ks += 8) {
                float af[2][4];
#pragma unroll
                for (int i = 0; i < 2; i++) {
                    int base = 16 * i;
                    af[i][0] = S[(base + gid) * SP + mc + ks + tig];
                    af[i][1] = S[(base + gid + 8) * SP + mc + ks + tig];
                    af[i][2] = S[(base + gid) * SP + mc + ks + tig + 4];
                    af[i][3] = S[(base + gid + 8) * SP + mc + ks + tig + 4];
                }
                float bf[4][2];
#pragma unroll
                for (int j = 0; j < 4; j++) {
                    bf[j][0] = cs[(ks + tig) * 260 + wv0 + 8 * j + gid];
                    bf[j][1] = cs[(ks + tig + 4) * 260 + wv0 + 8 * j + gid];
                }
#pragma unroll
                for (int i = 0; i < 2; i++)
#pragma unroll
                    for (int j = 0; j < 4; j++)
                        mma_tf32(acc3[i][j], af[i], bf[j], acc3[i][j]);
            }
        }
        __syncthreads();   // all warps done reading S

        // stage O^T [v][n] into S region (stride 36), then coalesced write
#pragma unroll
        for (int i = 0; i < 2; i++)
#pragma unroll
            for (int j = 0; j < 4; j++) {
                int nn = 16 * i + gid;
                int vv = wv0 + 8 * j + 2 * tig;
                S[vv * 36 + nn]           = acc3[i][j][0];
                S[(vv + 1) * 36 + nn]     = acc3[i][j][1];
                S[vv * 36 + nn + 8]       = acc3[i][j][2];
                S[(vv + 1) * 36 + nn + 8] = acc3[i][j][3];
            }
        __syncthreads();

        float* ob = g_o + (size_t)b * 256 * NPIX;
        for (int it = 0; it < 32; it++) {
            int vv = wid + 8 * it;
            ob[(size_t)vv * NPIX + n0g + lane] = S[vv * 36 + lane];
        }
    }
}

// ---------------- launch ----------------
extern "C" void kernel_launch(void* const* d_in, const int* in_sizes, int n_in,
                              void* d_out, int out_size)
{
    const float* x      = (const float*)d_in[0];
    const float* wtheta = (const float*)d_in[1];
    const float* wphi   = (const float*)d_in[2];
    const float* wg     = (const float*)d_in[3];
    const float* wo     = (const float*)d_in[4];
    const float* gamma  = (const float*)d_in[5];
    float* out = (float*)d_out;

    float *dW, *dY, *dO;
    cudaGetSymbolAddress((void**)&dW, g_Wcat);
    cudaGetSymbolAddress((void**)&dY, g_Y);
    cudaGetSymbolAddress((void**)&dO, g_o);

    cudaFuncSetAttribute(attn_kernel,
                         cudaFuncAttributeMaxDynamicSharedMemorySize, ATTN_SMEM);

    // 1) concat weights
    catw_kernel<<<(384 * 512 + 255) / 256, 256>>>(wtheta, wphi, wg);

    // 2) projections: Y[b] = Wcat @ x[b]   (M=384, K=512, N=4096)
    {
        dim3 grid(NPIX / BN, 384 / BM, BATCH);
        gemm_tf32_kernel<<<grid, 256>>>(dW, x, dY, 384, 512, NPIX, nullptr, nullptr);
    }

    // 3) 2x2 maxpool -> phi, g^T (tf32)
    pool_kernel<<<(BATCH * 320 * MPIX + 255) / 256, 256>>>();

    // 4) fused attention -> o
    {
        dim3 grid(NPIX / 32, BATCH);
        attn_kernel<<<grid, 256, ATTN_SMEM>>>();
    }

    // 5) out = gamma * (w_o @ o) + x   (M=512, K=256, N=4096)
    {
        dim3 grid(NPIX / BN, 512 / BM, BATCH);
        gemm_tf32_kernel<<<grid, 256>>>(wo, dO, out, 512, 256, NPIX, gamma, x);
    }
}

// round 5
// speedup vs baseline: 3.9368x; 1.6695x over previous
#include <cuda_runtime.h>
#include <cuda_bf16.h>
#include <math.h>

#define BATCH 16
#define NPIX  4096   // 64*64
#define MPIX  1024   // 32*32

// ---------------- scratch (device globals; no allocation) ----------------
__device__ float    g_Wcat[384 * 512];
__device__ float    g_Y[(size_t)BATCH * 384 * NPIX];          // projections
__device__ unsigned g_phip[(size_t)BATCH * 32 * MPIX];        // [b][d/2][m]  bf16x2(d,d+1)
__device__ unsigned g_gp[(size_t)BATCH * 512 * 256];          // [b][m/2][v]  bf16x2(m,m+1)
__device__ float    g_o[(size_t)BATCH * 256 * NPIX];          // attention out [b][v][n]

// ---------------- helpers ----------------
__device__ __forceinline__ float to_tf32(float x) {
    float r;
    asm("cvt.rna.tf32.f32 %0, %1;" : "=f"(r) : "f"(x));
    return r;
}
__device__ __forceinline__ unsigned packbf(float lo, float hi) {
    __nv_bfloat162 h = __floats2bfloat162_rn(lo, hi);
    return *(unsigned*)&h;
}
__device__ __forceinline__ float2 unpackbf(unsigned u) {
    __nv_bfloat162 h = *(__nv_bfloat162*)&u;
    return __bfloat1622float2(h);
}
__device__ __forceinline__ void mma_tf32(float* d, const float* a, const float* b,
                                         const float* c)
{
    asm volatile(
        "mma.sync.aligned.m16n8k8.row.col.f32.tf32.tf32.f32 "
        "{%0,%1,%2,%3}, {%4,%5,%6,%7}, {%8,%9}, {%10,%11,%12,%13};\n"
        : "=f"(d[0]), "=f"(d[1]), "=f"(d[2]), "=f"(d[3])
        : "r"(__float_as_uint(a[0])), "r"(__float_as_uint(a[1])),
          "r"(__float_as_uint(a[2])), "r"(__float_as_uint(a[3])),
          "r"(__float_as_uint(b[0])), "r"(__float_as_uint(b[1])),
          "f"(c[0]), "f"(c[1]), "f"(c[2]), "f"(c[3]));
}
__device__ __forceinline__ void mma_bf16(float* d, const unsigned* a, const unsigned* b,
                                         const float* c)
{
    asm volatile(
        "mma.sync.aligned.m16n8k16.row.col.f32.bf16.bf16.f32 "
        "{%0,%1,%2,%3}, {%4,%5,%6,%7}, {%8,%9}, {%10,%11,%12,%13};\n"
        : "=f"(d[0]), "=f"(d[1]), "=f"(d[2]), "=f"(d[3])
        : "r"(a[0]), "r"(a[1]), "r"(a[2]), "r"(a[3]),
          "r"(b[0]), "r"(b[1]),
          "f"(c[0]), "f"(c[1]), "f"(c[2]), "f"(c[3]));
}

// ---------------- weight concat ----------------
__global__ void catw_kernel(const float* __restrict__ wt, const float* __restrict__ wp,
                            const float* __restrict__ wg)
{
    int t = blockIdx.x * blockDim.x + threadIdx.x;
    if (t >= 384 * 512) return;
    int row = t >> 9;
    float v;
    if (row < 64)       v = wt[t];
    else if (row < 128) v = wp[t - 64 * 512];
    else                v = wg[t - 128 * 512];
    g_Wcat[t] = v;
}

// ---------------- TF32 tensor-core GEMM (unchanged from R3) ----------------
#define BM 128
#define BN 128
#define BK 16
#define AS_STRIDE 20
#define BS_STRIDE 132
__global__ void __launch_bounds__(256, 2) gemm_tf32_kernel(
    const float* __restrict__ A, const float* __restrict__ Bbase, float* __restrict__ Cbase,
    int M, int K, int N,
    const float* __restrict__ gamma, const float* __restrict__ resid)
{
    int b = blockIdx.z;
    const float* B = Bbase + (size_t)b * K * N;
    float* C = Cbase + (size_t)b * M * N;
    int m0 = blockIdx.y * BM;
    int n0 = blockIdx.x * BN;

    __shared__ float As[BM][AS_STRIDE];
    __shared__ float Bs[BK][BS_STRIDE];

    int tx   = threadIdx.x;
    int wid  = tx >> 5;
    int lane = tx & 31;
    int gid  = lane >> 2;
    int tig  = lane & 3;
    int wm0  = (wid & 1) * 64;
    int wn0  = (wid >> 1) * 32;

    float acc[4][4][4];
#pragma unroll
    for (int i = 0; i < 4; i++)
#pragma unroll
        for (int j = 0; j < 4; j++)
#pragma unroll
            for (int q = 0; q < 4; q++) acc[i][j][q] = 0.f;

    int a_row[2], a_col[2], b_row[2], b_col[2];
#pragma unroll
    for (int r = 0; r < 2; r++) {
        int idx = tx + 256 * r;
        a_row[r] = idx >> 2;  a_col[r] = (idx & 3) * 4;
        b_row[r] = idx >> 5;  b_col[r] = (idx & 31) * 4;
    }

    float4 pa[2], pb[2];
#pragma unroll
    for (int r = 0; r < 2; r++) {
        pa[r] = *(const float4*)&A[(size_t)(m0 + a_row[r]) * K + a_col[r]];
        pb[r] = *(const float4*)&B[(size_t)b_row[r] * N + n0 + b_col[r]];
    }

    for (int k0 = 0; k0 < K; k0 += BK) {
        __syncthreads();
#pragma unroll
        for (int r = 0; r < 2; r++) {
            float4 va = pa[r], vb = pb[r];
            va.x = to_tf32(va.x); va.y = to_tf32(va.y);
            va.z = to_tf32(va.z); va.w = to_tf32(va.w);
            vb.x = to_tf32(vb.x); vb.y = to_tf32(vb.y);
            vb.z = to_tf32(vb.z); vb.w = to_tf32(vb.w);
            *(float4*)&As[a_row[r]][a_col[r]] = va;
            *(float4*)&Bs[b_row[r]][b_col[r]] = vb;
        }
        __syncthreads();

        if (k0 + BK < K) {
#pragma unroll
            for (int r = 0; r < 2; r++) {
                pa[r] = *(const float4*)&A[(size_t)(m0 + a_row[r]) * K + k0 + BK + a_col[r]];
                pb[r] = *(const float4*)&B[(size_t)(k0 + BK + b_row[r]) * N + n0 + b_col[r]];
            }
        }

#pragma unroll
        for (int ks = 0; ks < BK; ks += 8) {
            float af[4][4];
#pragma unroll
            for (int i = 0; i < 4; i++) {
                int base = wm0 + 16 * i;
                af[i][0] = As[base + gid][ks + tig];
                af[i][1] = As[base + gid + 8][ks + tig];
                af[i][2] = As[base + gid][ks + tig + 4];
                af[i][3] = As[base + gid + 8][ks + tig + 4];
            }
            float bf[4][2];
#pragma unroll
            for (int j = 0; j < 4; j++) {
                bf[j][0] = Bs[ks + tig][wn0 + 8 * j + gid];
                bf[j][1] = Bs[ks + tig + 4][wn0 + 8 * j + gid];
            }
#pragma unroll
            for (int i = 0; i < 4; i++)
#pragma unroll
                for (int j = 0; j < 4; j++)
                    mma_tf32(acc[i][j], af[i], bf[j], acc[i][j]);
        }
    }

    if (resid != nullptr) {
        float gm = gamma[0];
#pragma unroll
        for (int i = 0; i < 4; i++) {
            int r0 = m0 + wm0 + 16 * i + gid;
#pragma unroll
            for (int j = 0; j < 4; j++) {
                int cc = n0 + wn0 + 8 * j + 2 * tig;
                const float* rr0 = resid + (size_t)b * M * N + (size_t)r0 * N + cc;
                const float* rr1 = rr0 + 8 * N;
                float2 v0 = make_float2(gm * acc[i][j][0] + rr0[0], gm * acc[i][j][1] + rr0[1]);
                float2 v1 = make_float2(gm * acc[i][j][2] + rr1[0], gm * acc[i][j][3] + rr1[1]);
                *(float2*)&C[(size_t)r0 * N + cc]       = v0;
                *(float2*)&C[(size_t)(r0 + 8) * N + cc] = v1;
            }
        }
    } else {
#pragma unroll
        for (int i = 0; i < 4; i++) {
            int r0 = m0 + wm0 + 16 * i + gid;
#pragma unroll
            for (int j = 0; j < 4; j++) {
                int cc = n0 + wn0 + 8 * j + 2 * tig;
                *(float2*)&C[(size_t)r0 * N + cc]       = make_float2(acc[i][j][0], acc[i][j][1]);
                *(float2*)&C[(size_t)(r0 + 8) * N + cc] = make_float2(acc[i][j][2], acc[i][j][3]);
            }
        }
    }
}

// ---------------- 2x2 maxpool -> packed bf16x2 phi / g ----------------
__global__ void pool_kernel()
{
    int t = blockIdx.x * blockDim.x + threadIdx.x;
    const int NPHI = BATCH * 32 * MPIX;          // 524288
    if (t < NPHI) {
        int m  = t & 1023;
        int d2 = (t >> 10) & 31;
        int b  = t >> 15;
        int ph = m >> 5, pw = m & 31;
        int n00 = ph * 128 + pw * 2;
        const float* r0 = g_Y + ((size_t)b * 384 + 64 + 2 * d2) * NPIX;
        const float* r1 = r0 + NPIX;
        float v0 = fmaxf(fmaxf(r0[n00], r0[n00 + 1]), fmaxf(r0[n00 + 64], r0[n00 + 65]));
        float v1 = fmaxf(fmaxf(r1[n00], r1[n00 + 1]), fmaxf(r1[n00 + 64], r1[n00 + 65]));
        g_phip[((size_t)b * 32 + d2) * MPIX + m] = packbf(v0, v1);
    } else {
        int u = t - NPHI;
        if (u >= BATCH * 512 * 256) return;
        int m2 = u & 511;
        int v  = (u >> 9) & 255;
        int b  = u >> 17;
        int m  = 2 * m2;
        int ph = m >> 5, pw = m & 31;
        int n00 = ph * 128 + pw * 2;
        const float* row = g_Y + ((size_t)b * 384 + 128 + v) * NPIX;
        float v0 = fmaxf(fmaxf(row[n00],     row[n00 + 1]), fmaxf(row[n00 + 64], row[n00 + 65]));
        float v1 = fmaxf(fmaxf(row[n00 + 2], row[n00 + 3]), fmaxf(row[n00 + 66], row[n00 + 67]));
        g_gp[((size_t)b * 512 + m2) * 256 + v] = packbf(v0, v1);
    }
}

// ---------------- fused attention, bf16 MMA ----------------
// smem (u32): S32[32][520] | ts[32][36] | stg[32*264] | sinv[32]
#define S32S 520
#define TSS  36
#define PHS  136
#define GSS  264
#define ATTN_SMEM ((32 * S32S + 32 * TSS + 32 * GSS + 32) * 4)

__global__ void __launch_bounds__(256, 2) attn_kernel()
{
    extern __shared__ unsigned smu[];
    unsigned* S32  = smu;
    unsigned* ts   = smu + 32 * S32S;
    unsigned* stg  = ts + 32 * TSS;
    float*    sinv = (float*)(stg + 32 * GSS);

    int b    = blockIdx.y;
    int n0g  = blockIdx.x * 32;
    int tx   = threadIdx.x;
    int wid  = tx >> 5;
    int lane = tx & 31;
    int gid  = lane >> 2;
    int tig  = lane & 3;

    // theta tile packed along d: ts[n][d2]
    {
        const float* Yb = g_Y + (size_t)b * 384 * NPIX;
        for (int l = tx; l < 32 * 32; l += 256) {
            int n = l & 31, d2 = l >> 5;
            float t0 = Yb[(size_t)(2 * d2) * NPIX + n0g + n];
            float t1 = Yb[(size_t)(2 * d2 + 1) * NPIX + n0g + n];
            ts[n * TSS + d2] = packbf(t0, t1);
        }
    }

    // ---- phase 1: S = theta^T phi ----
    {
        const unsigned* ph = g_phip + (size_t)b * 32 * MPIX;
        for (int mc = 0; mc < MPIX; mc += 128) {
            __syncthreads();
#pragma unroll
            for (int r = 0; r < 4; r++) {
                int idx = tx + 256 * r;          // 1024 uint4
                int d2 = idx >> 5, c4 = (idx & 31) * 4;
                *(uint4*)&stg[d2 * PHS + c4] = *(const uint4*)&ph[(size_t)d2 * MPIX + mc + c4];
            }
            __syncthreads();

            float sacc[2][2][4];
#pragma unroll
            for (int i = 0; i < 2; i++)
#pragma unroll
                for (int j = 0; j < 2; j++)
#pragma unroll
                    for (int q = 0; q < 4; q++) sacc[i][j][q] = 0.f;

#pragma unroll
            for (int s = 0; s < 4; s++) {        // 4 k16 steps over d=64
                unsigned af[2][4];
#pragma unroll
                for (int i = 0; i < 2; i++) {
                    int base = 16 * i;
                    af[i][0] = ts[(base + gid) * TSS + 8 * s + tig];
                    af[i][1] = ts[(base + gid + 8) * TSS + 8 * s + tig];
                    af[i][2] = ts[(base + gid) * TSS + 8 * s + tig + 4];
                    af[i][3] = ts[(base + gid + 8) * TSS + 8 * s + tig + 4];
                }
                unsigned bfr[2][2];
#pragma unroll
                for (int j = 0; j < 2; j++) {
                    int col = wid * 16 + 8 * j + gid;
                    bfr[j][0] = stg[(8 * s + tig) * PHS + col];
                    bfr[j][1] = stg[(8 * s + tig + 4) * PHS + col];
                }
#pragma unroll
                for (int i = 0; i < 2; i++)
#pragma unroll
                    for (int j = 0; j < 2; j++)
                        mma_bf16(sacc[i][j], af[i], bfr[j], sacc[i][j]);
            }
#pragma unroll
            for (int i = 0; i < 2; i++)
#pragma unroll
                for (int j = 0; j < 2; j++) {
                    int rr  = 16 * i + gid;
                    int cc2 = (mc >> 1) + wid * 8 + 4 * j + tig;
                    S32[rr * S32S + cc2]       = packbf(sacc[i][j][0], sacc[i][j][1]);
                    S32[(rr + 8) * S32S + cc2] = packbf(sacc[i][j][2], sacc[i][j][3]);
                }
        }
    }
    __syncthreads();

    // ---- phase 2: softmax (store e as bf16; 1/sum applied in epilogue) ----
    {
        for (int rr = wid * 4; rr < wid * 4 + 4; rr++) {
            unsigned* row = S32 + rr * S32S;
            float mx = -1e30f;
            for (int i = lane; i < 512; i += 32) {
                float2 v = unpackbf(row[i]);
                mx = fmaxf(mx, fmaxf(v.x, v.y));
            }
#pragma unroll
            for (int off = 16; off; off >>= 1)
                mx = fmaxf(mx, __shfl_xor_sync(0xFFFFFFFFu, mx, off));
            float sum = 0.f;
            for (int i = lane; i < 512; i += 32) {
                float2 v = unpackbf(row[i]);
                float e0 = __expf(v.x - mx);
                float e1 = __expf(v.y - mx);
                sum += e0 + e1;
                row[i] = packbf(e0, e1);
            }
#pragma unroll
            for (int off = 16; off; off >>= 1)
                sum += __shfl_xor_sync(0xFFFFFFFFu, sum, off);
            if (lane == 0) sinv[rr] = 1.f / sum;
        }
    }
    __syncthreads();

    // ---- phase 3: O = P @ g ----
    {
        const unsigned* gp = g_gp + (size_t)b * 512 * 256;
        int wv0 = wid * 32;
        float acc3[2][4][4];
#pragma unroll
        for (int i = 0; i < 2; i++)
#pragma unroll
            for (int j = 0; j < 4; j++)
#pragma unroll
                for (int q = 0; q < 4; q++) acc3[i][j][q] = 0.f;

        for (int mc2 = 0; mc2 < 512; mc2 += 32) {    // 64 keys per chunk
            __syncthreads();
#pragma unroll
            for (int r = 0; r < 8; r++) {
                int idx = tx + 256 * r;              // 2048 uint4
                int mm = idx >> 6, c4 = (idx & 63) * 4;
                *(uint4*)&stg[mm * GSS + c4] = *(const uint4*)&gp[(size_t)(mc2 + mm) * 256 + c4];
            }
            __syncthreads();

#pragma unroll
            for (int s = 0; s < 4; s++) {            // 4 k16 steps over 64 keys
                unsigned af[2][4];
#pragma unroll
                for (int i = 0; i < 2; i++) {
                    int base = 16 * i;
                    af[i][0] = S32[(base + gid) * S32S + mc2 + 8 * s + tig];
                    af[i][1] = S32[(base + gid + 8) * S32S + mc2 + 8 * s + tig];
                    af[i][2] = S32[(base + gid) * S32S + mc2 + 8 * s + tig + 4];
                    af[i][3] = S32[(base + gid + 8) * S32S + mc2 + 8 * s + tig + 4];
                }
                unsigned bfr[4][2];
#pragma unroll
                for (int j = 0; j < 4; j++) {
                    int col = wv0 + 8 * j + gid;
                    bfr[j][0] = stg[(8 * s + tig) * GSS + col];
                    bfr[j][1] = stg[(8 * s + tig + 4) * GSS + col];
                }
#pragma unroll
                for (int i = 0; i < 2; i++)
#pragma unroll
                    for (int j = 0; j < 4; j++)
                        mma_bf16(acc3[i][j], af[i], bfr[j], acc3[i][j]);
            }
        }
        __syncthreads();   // all warps done reading S32/stg

        // stage O^T into S32 region (fp32, stride 36), scaled by 1/sum per row
        float* St = (float*)S32;
#pragma unroll
        for (int i = 0; i < 2; i++) {
            int nn = 16 * i + gid;
            float s0 = sinv[nn];
            float s1 = sinv[nn + 8];
#pragma unroll
            for (int j = 0; j < 4; j++) {
                int vv = wv0 + 8 * j + 2 * tig;
                St[vv * 36 + nn]           = acc3[i][j][0] * s0;
                St[(vv + 1) * 36 + nn]     = acc3[i][j][1] * s0;
                St[vv * 36 + nn + 8]       = acc3[i][j][2] * s1;
                St[(vv + 1) * 36 + nn + 8] = acc3[i][j][3] * s1;
            }
        }
        __syncthreads();

        float* ob = g_o + (size_t)b * 256 * NPIX;
        for (int it = 0; it < 32; it++) {
            int vv = wid + 8 * it;
            ob[(size_t)vv * NPIX + n0g + lane] = St[vv * 36 + lane];
        }
    }
}

// ---------------- launch ----------------
extern "C" void kernel_launch(void* const* d_in, const int* in_sizes, int n_in,
                              void* d_out, int out_size)
{
    const float* x      = (const float*)d_in[0];
    const float* wtheta = (const float*)d_in[1];
    const float* wphi   = (const float*)d_in[2];
    const float* wg     = (const float*)d_in[3];
    const float* wo     = (const float*)d_in[4];
    const float* gamma  = (const float*)d_in[5];
    float* out = (float*)d_out;

    float *dW, *dY, *dO;
    cudaGetSymbolAddress((void**)&dW, g_Wcat);
    cudaGetSymbolAddress((void**)&dY, g_Y);
    cudaGetSymbolAddress((void**)&dO, g_o);

    cudaFuncSetAttribute(attn_kernel,
                         cudaFuncAttributeMaxDynamicSharedMemorySize, ATTN_SMEM);

    // 1) concat weights
    catw_kernel<<<(384 * 512 + 255) / 256, 256>>>(wtheta, wphi, wg);

    // 2) projections: Y[b] = Wcat @ x[b]   (M=384, K=512, N=4096)
    {
        dim3 grid(NPIX / BN, 384 / BM, BATCH);
        gemm_tf32_kernel<<<grid, 256>>>(dW, x, dY, 384, 512, NPIX, nullptr, nullptr);
    }

    // 3) 2x2 maxpool -> packed phi, g
    {
        int total = BATCH * 32 * MPIX + BATCH * 512 * 256;
        pool_kernel<<<(total + 255) / 256, 256>>>();
    }

    // 4) fused attention -> o
    {
        dim3 grid(NPIX / 32, BATCH);
        attn_kernel<<<grid, 256, ATTN_SMEM>>>();
    }

    // 5) out = gamma * (w_o @ o) + x   (M=512, K=256, N=4096)
    {
        dim3 grid(NPIX / BN, 512 / BM, BATCH);
        gemm_tf32_kernel<<<grid, 256>>>(wo, dO, out, 512, 256, NPIX, gamma, x);
    }
}

// round 7
// speedup vs baseline: 5.0799x; 1.2904x over previous
#include <cuda_runtime.h>
#include <cuda_bf16.h>
#include <math.h>

#define BATCH 16
#define NPIX  4096   // 64*64
#define MPIX  1024   // 32*32

// ---------------- scratch (device globals; no allocation) ----------------
__device__ float    g_Wcat[384 * 512];
__device__ float    g_Y[(size_t)BATCH * 384 * NPIX];          // projections
__device__ unsigned g_phip[(size_t)BATCH * 32 * MPIX];        // [b][d/2][m]  bf16x2(d,d+1)
__device__ unsigned g_gp[(size_t)BATCH * 512 * 256];          // [b][m/2][v]  bf16x2(m,m+1)
__device__ float    g_o[(size_t)BATCH * 256 * NPIX];          // attention out [b][v][n]

// ---------------- helpers ----------------
__device__ __forceinline__ unsigned packbf(float lo, float hi) {
    __nv_bfloat162 h = __floats2bfloat162_rn(lo, hi);
    return *(unsigned*)&h;
}
__device__ __forceinline__ float2 unpackbf(unsigned u) {
    __nv_bfloat162 h = *(__nv_bfloat162*)&u;
    return __bfloat1622float2(h);
}
__device__ __forceinline__ void mma_bf16(float* d, const unsigned* a, const unsigned* b,
                                         const float* c)
{
    asm volatile(
        "mma.sync.aligned.m16n8k16.row.col.f32.bf16.bf16.f32 "
        "{%0,%1,%2,%3}, {%4,%5,%6,%7}, {%8,%9}, {%10,%11,%12,%13};\n"
        : "=f"(d[0]), "=f"(d[1]), "=f"(d[2]), "=f"(d[3])
        : "r"(a[0]), "r"(a[1]), "r"(a[2]), "r"(a[3]),
          "r"(b[0]), "r"(b[1]),
          "f"(c[0]), "f"(c[1]), "f"(c[2]), "f"(c[3]));
}
__device__ __forceinline__ void ldsm_x4(unsigned* r, unsigned saddr) {
    asm volatile(
        "ldmatrix.sync.aligned.m8n8.x4.shared.b16 {%0,%1,%2,%3}, [%4];"
        : "=r"(r[0]), "=r"(r[1]), "=r"(r[2]), "=r"(r[3]) : "r"(saddr));
}

// ---------------- weight concat ----------------
__global__ void catw_kernel(const float* __restrict__ wt, const float* __restrict__ wp,
                            const float* __restrict__ wg)
{
    int t = blockIdx.x * blockDim.x + threadIdx.x;
    if (t >= 384 * 512) return;
    int row = t >> 9;
    float v;
    if (row < 64)       v = wt[t];
    else if (row < 128) v = wp[t - 64 * 512];
    else                v = wg[t - 128 * 512];
    g_Wcat[t] = v;
}

// ---------------- BF16 tensor-core GEMM ----------------
// C[b] = A @ B[b]  (+ optional gamma*acc + resid)
// A: [M x K] fp32 row-major shared, B: [K x N] fp32 row-major per batch.
// M%128==0, N%128==0, K%32==0.
#define ASU 20    // As u32 stride (16 k-pairs + pad)
#define BSU 136   // Bs u32 stride
__global__ void __launch_bounds__(256, 2) gemm_bf16_kernel(
    const float* __restrict__ A, const float* __restrict__ Bbase, float* __restrict__ Cbase,
    int M, int K, int N,
    const float* __restrict__ gamma, const float* __restrict__ resid)
{
    int b = blockIdx.z;
    const float* B = Bbase + (size_t)b * K * N;
    float* C = Cbase + (size_t)b * M * N;
    int m0 = blockIdx.y * 128;
    int n0 = blockIdx.x * 128;

    __shared__ unsigned As[128 * ASU];   // [m][k2]
    __shared__ unsigned Bs[16 * BSU];    // [k2][n]

    int tx   = threadIdx.x;
    int wid  = tx >> 5;
    int lane = tx & 31;
    int gid  = lane >> 2;
    int tig  = lane & 3;
    int wm0  = (wid & 1) * 64;
    int wn0  = (wid >> 1) * 32;
    int lr   = (lane & 7) + ((lane >> 3) & 1) * 8;   // ldmatrix row-in-16
    int lkc  = (lane >> 4) * 4;                      // ldmatrix u32-col offset

    unsigned as_base = (unsigned)__cvta_generic_to_shared(As);
    unsigned ldsm_addr[4];
#pragma unroll
    for (int i = 0; i < 4; i++)
        ldsm_addr[i] = as_base + ((wm0 + 16 * i + lr) * ASU + lkc) * 4;

    float acc[4][4][4];
#pragma unroll
    for (int i = 0; i < 4; i++)
#pragma unroll
        for (int j = 0; j < 4; j++)
#pragma unroll
            for (int q = 0; q < 4; q++) acc[i][j][q] = 0.f;

    for (int k0 = 0; k0 < K; k0 += 32) {
        __syncthreads();
        // stage A: 128x32 fp32 -> bf16x2 (k-pairs packed): 1024 float4 groups
#pragma unroll
        for (int r = 0; r < 4; r++) {
            int idx = tx + 256 * r;
            int am  = idx >> 3;
            int ak4 = (idx & 7) * 4;
            float4 v = *(const float4*)&A[(size_t)(m0 + am) * K + k0 + ak4];
            unsigned u0 = packbf(v.x, v.y);
            unsigned u1 = packbf(v.z, v.w);
            *(uint2*)&As[am * ASU + (ak4 >> 1)] = make_uint2(u0, u1);
        }
        // stage B: 32x128 fp32 -> Bs[k2][n] bf16x2(k,k+1): 16*32 = 512 groups
#pragma unroll
        for (int r = 0; r < 2; r++) {
            int idx = tx + 256 * r;
            int k2  = idx >> 5;
            int n4  = (idx & 31) * 4;
            const float* p0 = &B[(size_t)(k0 + 2 * k2) * N + n0 + n4];
            float4 u = *(const float4*)p0;
            float4 w = *(const float4*)(p0 + N);
            uint4 pv = make_uint4(packbf(u.x, w.x), packbf(u.y, w.y),
                                  packbf(u.z, w.z), packbf(u.w, w.w));
            *(uint4*)&Bs[k2 * BSU + n4] = pv;
        }
        __syncthreads();

#pragma unroll
        for (int s = 0; s < 2; s++) {
            unsigned af[4][4];
#pragma unroll
            for (int i = 0; i < 4; i++)
                ldsm_x4(af[i], ldsm_addr[i] + s * 32);
            unsigned bfr[4][2];
#pragma unroll
            for (int j = 0; j < 4; j++) {
                int col = wn0 + 8 * j + gid;
                bfr[j][0] = Bs[(8 * s + tig) * BSU + col];
                bfr[j][1] = Bs[(8 * s + tig + 4) * BSU + col];
            }
#pragma unroll
            for (int i = 0; i < 4; i++)
#pragma unroll
                for (int j = 0; j < 4; j++)
                    mma_bf16(acc[i][j], af[i], bfr[j], acc[i][j]);
        }
    }

    // epilogue
    if (resid != nullptr) {
        float gm = gamma[0];
#pragma unroll
        for (int i = 0; i < 4; i++) {
            int r0 = m0 + wm0 + 16 * i + gid;
#pragma unroll
            for (int j = 0; j < 4; j++) {
                int cc = n0 + wn0 + 8 * j + 2 * tig;
                const float* rr0 = resid + (size_t)b * M * N + (size_t)r0 * N + cc;
                const float* rr1 = rr0 + 8 * N;
                float2 v0 = make_float2(gm * acc[i][j][0] + rr0[0], gm * acc[i][j][1] + rr0[1]);
                float2 v1 = make_float2(gm * acc[i][j][2] + rr1[0], gm * acc[i][j][3] + rr1[1]);
                *(float2*)&C[(size_t)r0 * N + cc]       = v0;
                *(float2*)&C[(size_t)(r0 + 8) * N + cc] = v1;
            }
        }
    } else {
#pragma unroll
        for (int i = 0; i < 4; i++) {
            int r0 = m0 + wm0 + 16 * i + gid;
#pragma unroll
            for (int j = 0; j < 4; j++) {
                int cc = n0 + wn0 + 8 * j + 2 * tig;
                *(float2*)&C[(size_t)r0 * N + cc]       = make_float2(acc[i][j][0], acc[i][j][1]);
                *(float2*)&C[(size_t)(r0 + 8) * N + cc] = make_float2(acc[i][j][2], acc[i][j][3]);
            }
        }
    }
}

// ---------------- 2x2 maxpool -> packed bf16x2 phi / g ----------------
__global__ void pool_kernel()
{
    int t = blockIdx.x * blockDim.x + threadIdx.x;
    const int NPHI = BATCH * 32 * MPIX;          // 524288
    if (t < NPHI) {
        int m  = t & 1023;
        int d2 = (t >> 10) & 31;
        int b  = t >> 15;
        int ph = m >> 5, pw = m & 31;
        int n00 = ph * 128 + pw * 2;
        const float* r0 = g_Y + ((size_t)b * 384 + 64 + 2 * d2) * NPIX;
        const float* r1 = r0 + NPIX;
        float v0 = fmaxf(fmaxf(r0[n00], r0[n00 + 1]), fmaxf(r0[n00 + 64], r0[n00 + 65]));
        float v1 = fmaxf(fmaxf(r1[n00], r1[n00 + 1]), fmaxf(r1[n00 + 64], r1[n00 + 65]));
        g_phip[((size_t)b * 32 + d2) * MPIX + m] = packbf(v0, v1);
    } else {
        int u = t - NPHI;
        if (u >= BATCH * 512 * 256) return;
        int m2 = u & 511;
        int v  = (u >> 9) & 255;
        int b  = u >> 17;
        int m  = 2 * m2;
        int ph = m >> 5, pw = m & 31;
        int n00 = ph * 128 + pw * 2;
        const float* row = g_Y + ((size_t)b * 384 + 128 + v) * NPIX;
        float v0 = fmaxf(fmaxf(row[n00],     row[n00 + 1]), fmaxf(row[n00 + 64], row[n00 + 65]));
        float v1 = fmaxf(fmaxf(row[n00 + 2], row[n00 + 3]), fmaxf(row[n00 + 66], row[n00 + 67]));
        g_gp[((size_t)b * 512 + m2) * 256 + v] = packbf(v0, v1);
    }
}

// ---------------- fused attention, bf16 MMA + ldmatrix ----------------
// smem (u32): S32[32][516] | ts[32][36] | stg[8448] | sinv[32]
#define S32S 516
#define TSS  36
#define PHS  136
#define GSS  264
#define ATTN_SMEM ((32 * S32S + 32 * TSS + 8448 + 32) * 4)

__global__ void __launch_bounds__(256, 2) attn_kernel()
{
    extern __shared__ unsigned smu[];
    unsigned* S32  = smu;
    unsigned* ts   = smu + 32 * S32S;
    unsigned* stg  = ts + 32 * TSS;
    float*    sinv = (float*)(stg + 8448);

    int b    = blockIdx.y;
    int n0g  = blockIdx.x * 32;
    int tx   = threadIdx.x;
    int wid  = tx >> 5;
    int lane = tx & 31;
    int gid  = lane >> 2;
    int tig  = lane & 3;
    int lr   = (lane & 7) + ((lane >> 3) & 1) * 8;
    int lkc  = (lane >> 4) * 4;

    unsigned ts_sbase  = (unsigned)__cvta_generic_to_shared(ts);
    unsigned s32_sbase = (unsigned)__cvta_generic_to_shared(S32);

    // theta tile packed along d: ts[n][d2]
    {
        const float* Yb = g_Y + (size_t)b * 384 * NPIX;
        for (int l = tx; l < 32 * 32; l += 256) {
            int n = l & 31, d2 = l >> 5;
            float t0 = Yb[(size_t)(2 * d2) * NPIX + n0g + n];
            float t1 = Yb[(size_t)(2 * d2 + 1) * NPIX + n0g + n];
            ts[n * TSS + d2] = packbf(t0, t1);
        }
    }

    // ---- phase 1: S = theta^T phi ----
    {
        const unsigned* ph = g_phip + (size_t)b * 32 * MPIX;
        unsigned a_addr[2];
#pragma unroll
        for (int i = 0; i < 2; i++)
            a_addr[i] = ts_sbase + ((16 * i + lr) * TSS + lkc) * 4;

        for (int mc = 0; mc < MPIX; mc += 128) {
            __syncthreads();
#pragma unroll
            for (int r = 0; r < 4; r++) {
                int idx = tx + 256 * r;          // 1024 uint4
                int d2 = idx >> 5, c4 = (idx & 31) * 4;
                *(uint4*)&stg[d2 * PHS + c4] = *(const uint4*)&ph[(size_t)d2 * MPIX + mc + c4];
            }
            __syncthreads();

            float sacc[2][2][4];
#pragma unroll
            for (int i = 0; i < 2; i++)
#pragma unroll
                for (int j = 0; j < 2; j++)
#pragma unroll
                    for (int q = 0; q < 4; q++) sacc[i][j][q] = 0.f;

#pragma unroll
            for (int s = 0; s < 4; s++) {        // 4 k16 steps over d=64
                unsigned af[2][4];
#pragma unroll
                for (int i = 0; i < 2; i++)
                    ldsm_x4(af[i], a_addr[i] + s * 32);
                unsigned bfr[2][2];
#pragma unroll
                for (int j = 0; j < 2; j++) {
                    int col = wid * 16 + 8 * j + gid;
                    bfr[j][0] = stg[(8 * s + tig) * PHS + col];
                    bfr[j][1] = stg[(8 * s + tig + 4) * PHS + col];
                }
#pragma unroll
                for (int i = 0; i < 2; i++)
#pragma unroll
                    for (int j = 0; j < 2; j++)
                        mma_bf16(sacc[i][j], af[i], bfr[j], sacc[i][j]);
            }
#pragma unroll
            for (int i = 0; i < 2; i++)
#pragma unroll
                for (int j = 0; j < 2; j++) {
                    int rr  = 16 * i + gid;
                    int cc2 = (mc >> 1) + wid * 8 + 4 * j + tig;
                    S32[rr * S32S + cc2]       = packbf(sacc[i][j][0], sacc[i][j][1]);
                    S32[(rr + 8) * S32S + cc2] = packbf(sacc[i][j][2], sacc[i][j][3]);
                }
        }
    }
    __syncthreads();

    // ---- phase 2: softmax (store e as bf16; 1/sum applied in epilogue) ----
    {
        for (int rr = wid * 4; rr < wid * 4 + 4; rr++) {
            unsigned* row = S32 + rr * S32S;
            float mx = -1e30f;
            for (int i = lane; i < 512; i += 32) {
                float2 v = unpackbf(row[i]);
                mx = fmaxf(mx, fmaxf(v.x, v.y));
            }
#pragma unroll
            for (int off = 16; off; off >>= 1)
                mx = fmaxf(mx, __shfl_xor_sync(0xFFFFFFFFu, mx, off));
            float sum = 0.f;
            for (int i = lane; i < 512; i += 32) {
                float2 v = unpackbf(row[i]);
                float e0 = __expf(v.x - mx);
                float e1 = __expf(v.y - mx);
                sum += e0 + e1;
                row[i] = packbf(e0, e1);
            }
#pragma unroll
            for (int off = 16; off; off >>= 1)
                sum += __shfl_xor_sync(0xFFFFFFFFu, sum, off);
            if (lane == 0) sinv[rr] = 1.f / sum;
        }
    }
    __syncthreads();

    // ---- phase 3: O = P @ g ----
    {
        const unsigned* gp = g_gp + (size_t)b * 512 * 256;
        int wv0 = wid * 32;
        float acc3[2][4][4];
#pragma unroll
        for (int i = 0; i < 2; i++)
#pragma unroll
            for (int j = 0; j < 4; j++)
#pragma unroll
                for (int q = 0; q < 4; q++) acc3[i][j][q] = 0.f;

        for (int mc2 = 0; mc2 < 512; mc2 += 32) {    // 64 keys per chunk
            __syncthreads();
#pragma unroll
            for (int r = 0; r < 8; r++) {
                int idx = tx + 256 * r;              // 2048 uint4
                int mm = idx >> 6, c4 = (idx & 63) * 4;
                *(uint4*)&stg[mm * GSS + c4] = *(const uint4*)&gp[(size_t)(mc2 + mm) * 256 + c4];
            }
            __syncthreads();

#pragma unroll
            for (int s = 0; s < 4; s++) {            // 4 k16 steps over 64 keys
                unsigned af[2][4];
#pragma unroll
                for (int i = 0; i < 2; i++)
                    ldsm_x4(af[i], s32_sbase + ((16 * i + lr) * S32S + mc2 + 8 * s + lkc) * 4);
                unsigned bfr[4][2];
#pragma unroll
                for (int j = 0; j < 4; j++) {
                    int col = wv0 + 8 * j + gid;
                    bfr[j][0] = stg[(8 * s + tig) * GSS + col];
                    bfr[j][1] = stg[(8 * s + tig + 4) * GSS + col];
                }
#pragma unroll
                for (int i = 0; i < 2; i++)
#pragma unroll
                    for (int j = 0; j < 4; j++)
                        mma_bf16(acc3[i][j], af[i], bfr[j], acc3[i][j]);
            }
        }
        __syncthreads();   // all warps done reading S32/stg

        // stage O^T into S32 region (fp32, stride 36), scaled by 1/sum per row
        float* St = (float*)S32;
#pragma unroll
        for (int i = 0; i < 2; i++) {
            int nn = 16 * i + gid;
            float s0 = sinv[nn];
            float s1 = sinv[nn + 8];
#pragma unroll
            for (int j = 0; j < 4; j++) {
                int vv = wv0 + 8 * j + 2 * tig;
                St[vv * 36 + nn]           = acc3[i][j][0] * s0;
                St[(vv + 1) * 36 + nn]     = acc3[i][j][1] * s0;
                St[vv * 36 + nn + 8]       = acc3[i][j][2] * s1;
                St[(vv + 1) * 36 + nn + 8] = acc3[i][j][3] * s1;
            }
        }
        __syncthreads();

        float* ob = g_o + (size_t)b * 256 * NPIX;
        for (int it = 0; it < 32; it++) {
            int vv = wid + 8 * it;
            ob[(size_t)vv * NPIX + n0g + lane] = St[vv * 36 + lane];
        }
    }
}

// ---------------- launch ----------------
extern "C" void kernel_launch(void* const* d_in, const int* in_sizes, int n_in,
                              void* d_out, int out_size)
{
    const float* x      = (const float*)d_in[0];
    const float* wtheta = (const float*)d_in[1];
    const float* wphi   = (const float*)d_in[2];
    const float* wg     = (const float*)d_in[3];
    const float* wo     = (const float*)d_in[4];
    const float* gamma  = (const float*)d_in[5];
    float* out = (float*)d_out;

    float *dW, *dY, *dO;
    cudaGetSymbolAddress((void**)&dW, g_Wcat);
    cudaGetSymbolAddress((void**)&dY, g_Y);
    cudaGetSymbolAddress((void**)&dO, g_o);

    cudaFuncSetAttribute(attn_kernel,
                         cudaFuncAttributeMaxDynamicSharedMemorySize, ATTN_SMEM);

    // 1) concat weights
    catw_kernel<<<(384 * 512 + 255) / 256, 256>>>(wtheta, wphi, wg);

    // 2) projections: Y[b] = Wcat @ x[b]   (M=384, K=512, N=4096)
    {
        dim3 grid(NPIX / 128, 384 / 128, BATCH);
        gemm_bf16_kernel<<<grid, 256>>>(dW, x, dY, 384, 512, NPIX, nullptr, nullptr);
    }

    // 3) 2x2 maxpool -> packed phi, g
    {
        int total = BATCH * 32 * MPIX + BATCH * 512 * 256;
        pool_kernel<<<(total + 255) / 256, 256>>>();
    }

    // 4) fused attention -> o
    {
        dim3 grid(NPIX / 32, BATCH);
        attn_kernel<<<grid, 256, ATTN_SMEM>>>();
    }

    // 5) out = gamma * (w_o @ o) + x   (M=512, K=256, N=4096)
    {
        dim3 grid(NPIX / 128, 512 / 128, BATCH);
        gemm_bf16_kernel<<<grid, 256>>>(wo, dO, out, 512, 256, NPIX, gamma, x);
    }
}

// round 8
// speedup vs baseline: 7.5706x; 1.4903x over previous
#include <cuda_runtime.h>
#include <cuda_bf16.h>

#define BATCH 16
#define NPIX  4096   // 64*64
#define MPIX  1024   // 32*32

// ---------------- scratch (device globals; no allocation) ----------------
__device__ unsigned g_Wb[384 * 256];                       // [theta;phi;g] bf16x2 k-pairs
__device__ unsigned g_Wob[512 * 128];                      // w_o bf16x2 k-pairs
__device__ unsigned g_Xb[(size_t)BATCH * 256 * NPIX];      // x bf16x2 [b][k2][n]
__device__ float    g_Y[(size_t)BATCH * 384 * NPIX];       // projections fp32
__device__ unsigned g_phq[(size_t)BATCH * 4 * 1024 * 8];   // phi repack (see pool)
__device__ unsigned g_gq[(size_t)BATCH * 64 * 256 * 8];    // g   repack (see pool)
__device__ unsigned g_Ob[(size_t)BATCH * 128 * NPIX];      // attn out bf16x2 [b][v2][n]

// ---------------- helpers ----------------
__device__ __forceinline__ unsigned packbf(float lo, float hi) {
    __nv_bfloat162 h = __floats2bfloat162_rn(lo, hi);
    return *(unsigned*)&h;
}
__device__ __forceinline__ float2 unpackbf(unsigned u) {
    __nv_bfloat162 h = *(__nv_bfloat162*)&u;
    return __bfloat1622float2(h);
}
__device__ __forceinline__ void mma_bf16(float* d, const unsigned* a, const unsigned* b,
                                         const float* c)
{
    asm volatile(
        "mma.sync.aligned.m16n8k16.row.col.f32.bf16.bf16.f32 "
        "{%0,%1,%2,%3}, {%4,%5,%6,%7}, {%8,%9}, {%10,%11,%12,%13};\n"
        : "=f"(d[0]), "=f"(d[1]), "=f"(d[2]), "=f"(d[3])
        : "r"(a[0]), "r"(a[1]), "r"(a[2]), "r"(a[3]),
          "r"(b[0]), "r"(b[1]),
          "f"(c[0]), "f"(c[1]), "f"(c[2]), "f"(c[3]));
}
__device__ __forceinline__ void ldsm_x4(unsigned* r, unsigned saddr) {
    asm volatile(
        "ldmatrix.sync.aligned.m8n8.x4.shared.b16 {%0,%1,%2,%3}, [%4];"
        : "=r"(r[0]), "=r"(r[1]), "=r"(r[2]), "=r"(r[3]) : "r"(saddr));
}
#define CP16(dst, src) \
    asm volatile("cp.async.cg.shared.global [%0], [%1], 16;\n" :: "r"(dst), "l"(src))

// ---------------- weight convert/concat -> bf16 pairs ----------------
__global__ void wcvt_kernel(const float* __restrict__ wt, const float* __restrict__ wp,
                            const float* __restrict__ wg, const float* __restrict__ wo)
{
    int t = blockIdx.x * blockDim.x + threadIdx.x;
    if (t < 384 * 256) {
        int row = t >> 8, k2 = t & 255;
        const float* src;
        if (row < 64)       src = wt + (size_t)row * 512;
        else if (row < 128) src = wp + (size_t)(row - 64) * 512;
        else                src = wg + (size_t)(row - 128) * 512;
        g_Wb[t] = packbf(src[2 * k2], src[2 * k2 + 1]);
    } else {
        int u = t - 384 * 256;
        if (u >= 512 * 128) return;
        int row = u >> 7, k2 = u & 127;
        g_Wob[u] = packbf(wo[(size_t)row * 256 + 2 * k2], wo[(size_t)row * 256 + 2 * k2 + 1]);
    }
}

// ---------------- x convert: fp32 -> bf16x2 [b][k2][n] ----------------
__global__ void xcvt_kernel(const float* __restrict__ x)
{
    int t = blockIdx.x * blockDim.x + threadIdx.x;   // 16*256*1024
    int n4 = (t & 1023) * 4;
    int k2 = (t >> 10) & 255;
    int b  = t >> 18;
    const float* p0 = x + ((size_t)b * 512 + 2 * k2) * NPIX + n4;
    float4 u = *(const float4*)p0;
    float4 w = *(const float4*)(p0 + NPIX);
    uint4 pv = make_uint4(packbf(u.x, w.x), packbf(u.y, w.y),
                          packbf(u.z, w.z), packbf(u.w, w.w));
    *(uint4*)&g_Xb[((size_t)b * 256 + k2) * NPIX + n4] = pv;
}

// ---------------- BF16 GEMM with cp.async double-buffered staging ----------------
// C[b] = A @ B[b]; A: [M][K2] u32 bf16x2 (shared), B: [b][K2][N] u32 bf16x2.
// M%128==0, N%128==0, K2%16==0.
#define ASU 20
#define BSU 136
__global__ void __launch_bounds__(256, 2) gemm_async(
    const unsigned* __restrict__ A, const unsigned* __restrict__ Bbase,
    float* __restrict__ Cbase,
    int M, int K2, int N,
    const float* __restrict__ gamma, const float* __restrict__ resid)
{
    int b = blockIdx.z;
    const unsigned* B = Bbase + (size_t)b * K2 * N;
    float* C = Cbase + (size_t)b * M * N;
    int m0 = blockIdx.y * 128;
    int n0 = blockIdx.x * 128;

    __shared__ unsigned As[2][128 * ASU];
    __shared__ unsigned Bs[2][16 * BSU];

    int tx   = threadIdx.x;
    int wid  = tx >> 5;
    int lane = tx & 31;
    int gid  = lane >> 2;
    int tig  = lane & 3;
    int wm0  = (wid & 1) * 64;
    int wn0  = (wid >> 1) * 32;
    int lr   = (lane & 7) + ((lane >> 3) & 1) * 8;
    int lkc  = (lane >> 4) * 4;

    unsigned asb[2], bsb[2];
    asb[0] = (unsigned)__cvta_generic_to_shared(&As[0][0]);
    asb[1] = (unsigned)__cvta_generic_to_shared(&As[1][0]);
    bsb[0] = (unsigned)__cvta_generic_to_shared(&Bs[0][0]);
    bsb[1] = (unsigned)__cvta_generic_to_shared(&Bs[1][0]);

    float acc[4][4][4];
#pragma unroll
    for (int i = 0; i < 4; i++)
#pragma unroll
        for (int j = 0; j < 4; j++)
#pragma unroll
            for (int q = 0; q < 4; q++) acc[i][j][q] = 0.f;

    // async stage: A tile 128x16 u32 (512x16B), B tile 16x128 u32 (512x16B)
    auto stage = [&](int k02, int p) {
#pragma unroll
        for (int r = 0; r < 2; r++) {
            int idx = tx + 256 * r;
            int am = idx >> 2, c4 = (idx & 3) * 4;
            CP16(asb[p] + (am * ASU + c4) * 4,
                 (const void*)&A[(size_t)(m0 + am) * K2 + k02 + c4]);
            int kr = idx >> 5, n4 = (idx & 31) * 4;
            CP16(bsb[p] + (kr * BSU + n4) * 4,
                 (const void*)&B[(size_t)(k02 + kr) * N + n0 + n4]);
        }
        asm volatile("cp.async.commit_group;\n");
    };

    stage(0, 0);
    int p = 0;
    for (int k02 = 0; k02 < K2; k02 += 16) {
        __syncthreads();                    // buffer p^1 free to overwrite
        bool nxt = (k02 + 16 < K2);
        if (nxt) {
            stage(k02 + 16, p ^ 1);
            asm volatile("cp.async.wait_group 1;\n");
        } else {
            asm volatile("cp.async.wait_group 0;\n");
        }
        __syncthreads();                    // buffer p visible to all

#pragma unroll
        for (int s = 0; s < 2; s++) {
            unsigned af[4][4];
#pragma unroll
            for (int i = 0; i < 4; i++)
                ldsm_x4(af[i], asb[p] + ((wm0 + 16 * i + lr) * ASU + lkc) * 4 + s * 32);
            unsigned bfr[4][2];
#pragma unroll
            for (int j = 0; j < 4; j++) {
                int col = wn0 + 8 * j + gid;
                bfr[j][0] = Bs[p][(8 * s + tig) * BSU + col];
                bfr[j][1] = Bs[p][(8 * s + tig + 4) * BSU + col];
            }
#pragma unroll
            for (int i = 0; i < 4; i++)
#pragma unroll
                for (int j = 0; j < 4; j++)
                    mma_bf16(acc[i][j], af[i], bfr[j], acc[i][j]);
        }
        p ^= 1;
    }

    if (resid != nullptr) {
        float gm = gamma[0];
#pragma unroll
        for (int i = 0; i < 4; i++) {
            int r0 = m0 + wm0 + 16 * i + gid;
#pragma unroll
            for (int j = 0; j < 4; j++) {
                int cc = n0 + wn0 + 8 * j + 2 * tig;
                const float* rr0 = resid + (size_t)b * M * N + (size_t)r0 * N + cc;
                const float* rr1 = rr0 + 8 * N;
                float2 v0 = make_float2(gm * acc[i][j][0] + rr0[0], gm * acc[i][j][1] + rr0[1]);
                float2 v1 = make_float2(gm * acc[i][j][2] + rr1[0], gm * acc[i][j][3] + rr1[1]);
                *(float2*)&C[(size_t)r0 * N + cc]       = v0;
                *(float2*)&C[(size_t)(r0 + 8) * N + cc] = v1;
            }
        }
    } else {
#pragma unroll
        for (int i = 0; i < 4; i++) {
            int r0 = m0 + wm0 + 16 * i + gid;
#pragma unroll
            for (int j = 0; j < 4; j++) {
                int cc = n0 + wn0 + 8 * j + 2 * tig;
                *(float2*)&C[(size_t)r0 * N + cc]       = make_float2(acc[i][j][0], acc[i][j][1]);
                *(float2*)&C[(size_t)(r0 + 8) * N + cc] = make_float2(acc[i][j][2], acc[i][j][3]);
            }
        }
    }
}

// ---------------- 2x2 maxpool -> MMA-fragment-ordered bf16 layouts ----------------
// phi:  u32 idx = (((b*4+s)*1024+m)*4+tig)*2+slot,  d2 = 8s+tig+4*slot
// g:    u32 idx = (((b*64+kk)*256+v)*4+tig)*2+slot, m2 = 8kk+tig+4*slot
__global__ void pool_kernel()
{
    int t = blockIdx.x * blockDim.x + threadIdx.x;
    const int NPHI = BATCH * 32 * MPIX;          // 524288
    if (t < NPHI) {
        int m  = t & 1023;
        int d2 = (t >> 10) & 31;
        int b  = t >> 15;
        int ph = m >> 5, pw = m & 31;
        int n00 = ph * 128 + pw * 2;
        const float* r0 = g_Y + ((size_t)b * 384 + 64 + 2 * d2) * NPIX;
        const float* r1 = r0 + NPIX;
        float v0 = fmaxf(fmaxf(r0[n00], r0[n00 + 1]), fmaxf(r0[n00 + 64], r0[n00 + 65]));
        float v1 = fmaxf(fmaxf(r1[n00], r1[n00 + 1]), fmaxf(r1[n00 + 64], r1[n00 + 65]));
        int s = d2 >> 3, tig = d2 & 3, slot = (d2 >> 2) & 1;
        g_phq[((((size_t)b * 4 + s) * 1024 + m) * 4 + tig) * 2 + slot] = packbf(v0, v1);
    } else {
        int u = t - NPHI;
        if (u >= BATCH * 512 * 256) return;
        int m2 = u & 511;
        int v  = (u >> 9) & 255;
        int b  = u >> 17;
        int m  = 2 * m2;
        int ph = m >> 5, pw = m & 31;
        int n00 = ph * 128 + pw * 2;
        const float* row = g_Y + ((size_t)b * 384 + 128 + v) * NPIX;
        float v0 = fmaxf(fmaxf(row[n00],     row[n00 + 1]), fmaxf(row[n00 + 64], row[n00 + 65]));
        float v1 = fmaxf(fmaxf(row[n00 + 2], row[n00 + 3]), fmaxf(row[n00 + 66], row[n00 + 67]));
        int kk = m2 >> 3, tig = m2 & 3, slot = (m2 >> 2) & 1;
        g_gq[((((size_t)b * 64 + kk) * 256 + v) * 4 + tig) * 2 + slot] = packbf(v0, v1);
    }
}

// ---------------- fused attention: direct-LDG B frags, no staging ----------------
// smem (u32): S32[32][516] | ts[32][36] | sinv[32]
#define S32S 516
#define TSS  36
#define ATTN_SMEM ((32 * S32S + 32 * TSS + 32) * 4)

__global__ void __launch_bounds__(256, 3) attn_kernel()
{
    extern __shared__ unsigned smu[];
    unsigned* S32  = smu;
    unsigned* ts   = smu + 32 * S32S;
    float*    sinv = (float*)(ts + 32 * TSS);

    int b    = blockIdx.y;
    int n0g  = blockIdx.x * 32;
    int tx   = threadIdx.x;
    int wid  = tx >> 5;
    int lane = tx & 31;
    int gid  = lane >> 2;
    int tig  = lane & 3;
    int lr   = (lane & 7) + ((lane >> 3) & 1) * 8;
    int lkc  = (lane >> 4) * 4;

    unsigned ts_sb  = (unsigned)__cvta_generic_to_shared(ts);
    unsigned s32_sb = (unsigned)__cvta_generic_to_shared(S32);

    // theta tile [n][d2] bf16-pairs
    {
        const float* Yb = g_Y + (size_t)b * 384 * NPIX;
        for (int l = tx; l < 32 * 32; l += 256) {
            int n = l & 31, d2 = l >> 5;
            ts[n * TSS + d2] = packbf(Yb[(size_t)(2 * d2) * NPIX + n0g + n],
                                      Yb[(size_t)(2 * d2 + 1) * NPIX + n0g + n]);
        }
    }
    __syncthreads();

    // ---- phase 1: S = theta^T phi; warp wid owns m-range [wid*128, wid*128+128) ----
    {
        const uint2* PH = (const uint2*)g_phq + (size_t)b * 4 * 1024 * 4;
        unsigned a_all[4][2][4];
#pragma unroll
        for (int s = 0; s < 4; s++)
#pragma unroll
            for (int i = 0; i < 2; i++)
                ldsm_x4(a_all[s][i], ts_sb + ((16 * i + lr) * TSS + s * 8 + lkc) * 4);

        int m0w = wid * 128;
#pragma unroll 2
        for (int mj = 0; mj < 16; mj++) {
            float sa0[4] = {0.f, 0.f, 0.f, 0.f};
            float sa1[4] = {0.f, 0.f, 0.f, 0.f};
#pragma unroll
            for (int s = 0; s < 4; s++) {
                uint2 q = PH[(size_t)s * 4096 + (m0w + 8 * mj) * 4 + lane];
                unsigned bfr[2] = {q.x, q.y};
                mma_bf16(sa0, a_all[s][0], bfr, sa0);
                mma_bf16(sa1, a_all[s][1], bfr, sa1);
            }
            int cc2 = wid * 64 + 4 * mj + tig;
            S32[gid * S32S + cc2]        = packbf(sa0[0], sa0[1]);
            S32[(gid + 8) * S32S + cc2]  = packbf(sa0[2], sa0[3]);
            S32[(gid + 16) * S32S + cc2] = packbf(sa1[0], sa1[1]);
            S32[(gid + 24) * S32S + cc2] = packbf(sa1[2], sa1[3]);
        }
    }
    __syncthreads();

    // ---- phase 2: softmax (store e as bf16; 1/sum applied in epilogue) ----
    {
        for (int rr = wid * 4; rr < wid * 4 + 4; rr++) {
            unsigned* row = S32 + rr * S32S;
            float mx = -1e30f;
            for (int i = lane; i < 512; i += 32) {
                float2 v = unpackbf(row[i]);
                mx = fmaxf(mx, fmaxf(v.x, v.y));
            }
#pragma unroll
            for (int off = 16; off; off >>= 1)
                mx = fmaxf(mx, __shfl_xor_sync(0xFFFFFFFFu, mx, off));
            float sum = 0.f;
            for (int i = lane; i < 512; i += 32) {
                float2 v = unpackbf(row[i]);
                float e0 = __expf(v.x - mx);
                float e1 = __expf(v.y - mx);
                sum += e0 + e1;
                row[i] = packbf(e0, e1);
            }
#pragma unroll
            for (int off = 16; off; off >>= 1)
                sum += __shfl_xor_sync(0xFFFFFFFFu, sum, off);
            if (lane == 0) sinv[rr] = 1.f / sum;
        }
    }
    __syncthreads();

    // ---- phase 3: O = P @ g; warp wid owns v-range [wid*32, wid*32+32) ----
    {
        const uint2* G2 = (const uint2*)g_gq + (size_t)b * 64 * 1024;
        int wv0 = wid * 32;
        float acc3[2][4][4];
#pragma unroll
        for (int i = 0; i < 2; i++)
#pragma unroll
            for (int j = 0; j < 4; j++)
#pragma unroll
                for (int q = 0; q < 4; q++) acc3[i][j][q] = 0.f;

        unsigned a_addr0 = s32_sb + (lr * S32S + lkc) * 4;
        unsigned a_addr1 = s32_sb + ((16 + lr) * S32S + lkc) * 4;

#pragma unroll 4
        for (int kk = 0; kk < 64; kk++) {
            uint2 q[4];
#pragma unroll
            for (int j = 0; j < 4; j++)
                q[j] = G2[(size_t)kk * 1024 + (wv0 + 8 * j) * 4 + lane];
            unsigned af0[4], af1[4];
            ldsm_x4(af0, a_addr0 + kk * 32);
            ldsm_x4(af1, a_addr1 + kk * 32);
#pragma unroll
            for (int j = 0; j < 4; j++) {
                unsigned bfr[2] = {q[j].x, q[j].y};
                mma_bf16(acc3[0][j], af0, bfr, acc3[0][j]);
                mma_bf16(acc3[1][j], af1, bfr, acc3[1][j]);
            }
        }
        __syncthreads();   // all warps done reading S32

        // stage O^T (fp32, stride 36) scaled by 1/sum
        float* St = (float*)S32;
#pragma unroll
        for (int i = 0; i < 2; i++) {
            int nn = 16 * i + gid;
            float s0 = sinv[nn];
            float s1 = sinv[nn + 8];
#pragma unroll
            for (int j = 0; j < 4; j++) {
                int vv = wv0 + 8 * j + 2 * tig;
                St[vv * 36 + nn]           = acc3[i][j][0] * s0;
                St[(vv + 1) * 36 + nn]     = acc3[i][j][1] * s0;
                St[vv * 36 + nn + 8]       = acc3[i][j][2] * s1;
                St[(vv + 1) * 36 + nn + 8] = acc3[i][j][3] * s1;
            }
        }
        __syncthreads();

        // packed bf16x2 output [b][v2][n]
        unsigned* ob = g_Ob + (size_t)b * 128 * NPIX;
        for (int it = 0; it < 16; it++) {
            int v2 = wid + 8 * it;
            ob[(size_t)v2 * NPIX + n0g + lane] =
                packbf(St[(2 * v2) * 36 + lane], St[(2 * v2 + 1) * 36 + lane]);
        }
    }
}

// ---------------- launch ----------------
extern "C" void kernel_launch(void* const* d_in, const int* in_sizes, int n_in,
                              void* d_out, int out_size)
{
    const float* x      = (const float*)d_in[0];
    const float* wtheta = (const float*)d_in[1];
    const float* wphi   = (const float*)d_in[2];
    const float* wg     = (const float*)d_in[3];
    const float* wo     = (const float*)d_in[4];
    const float* gamma  = (const float*)d_in[5];
    float* out = (float*)d_out;

    unsigned *dWb, *dWob, *dXb, *dOb;
    float *dY;
    cudaGetSymbolAddress((void**)&dWb,  g_Wb);
    cudaGetSymbolAddress((void**)&dWob, g_Wob);
    cudaGetSymbolAddress((void**)&dXb,  g_Xb);
    cudaGetSymbolAddress((void**)&dY,   g_Y);
    cudaGetSymbolAddress((void**)&dOb,  g_Ob);

    cudaFuncSetAttribute(attn_kernel,
                         cudaFuncAttributeMaxDynamicSharedMemorySize, ATTN_SMEM);

    // 1) weights -> bf16 pairs
    wcvt_kernel<<<(384 * 256 + 512 * 128 + 255) / 256, 256>>>(wtheta, wphi, wg, wo);

    // 2) x -> bf16 pairs
    xcvt_kernel<<<BATCH * 256 * 1024 / 256, 256>>>(x);

    // 3) projections: Y[b] = Wcat @ x[b]   (M=384, K2=256, N=4096)
    {
        dim3 grid(NPIX / 128, 384 / 128, BATCH);
        gemm_async<<<grid, 256>>>(dWb, dXb, dY, 384, 256, NPIX, nullptr, nullptr);
    }

    // 4) 2x2 maxpool -> fragment-ordered phi, g
    {
        int total = BATCH * 32 * MPIX + BATCH * 512 * 256;
        pool_kernel<<<(total + 255) / 256, 256>>>();
    }

    // 5) fused attention -> packed o
    {
        dim3 grid(NPIX / 32, BATCH);
        attn_kernel<<<grid, 256, ATTN_SMEM>>>();
    }

    // 6) out = gamma * (w_o @ o) + x   (M=512, K2=128, N=4096)
    {
        dim3 grid(NPIX / 128, 512 / 128, BATCH);
        gemm_async<<<grid, 256>>>(dWob, dOb, out, 512, 128, NPIX, gamma, x);
    }
}